// round 4
// baseline (speedup 1.0000x reference)
#include <cuda_runtime.h>

#define N_NODES 100000
#define N_EDGES 3200000
#define IN_F 128
#define HID 64
#define NC 16

// Scratch (static device globals — no allocation allowed)
__device__ __align__(16) float g_dinv[N_NODES];
__device__ __align__(16) float g_hs1 [N_NODES * HID];   // (x@W1)*dinv[row]
__device__ __align__(16) float g_agg1[N_NODES * HID];   // init = hs1 (self loop), += hs1[src]
__device__ __align__(16) float g_hs2 [N_NODES * NC];
__device__ __align__(16) float g_agg2[N_NODES * NC];
__device__ int g_is64;

// ---------------------------------------------------------------------------
// 0. detect whether edge_index is int64 or int32 (reads only first 4096 src
//    entries -> max byte offset 32KB, safe under both interpretations)
__global__ void k_detect(const long long* __restrict__ ei) {
    __shared__ int bad;
    if (threadIdx.x == 0) bad = 0;
    __syncthreads();
    for (int i = threadIdx.x; i < 4096; i += 256) {
        long long s = ei[i];
        if (s < 0 || s >= (long long)N_NODES) atomicOr(&bad, 1);
    }
    __syncthreads();
    if (threadIdx.x == 0) g_is64 = bad ? 0 : 1;
}

// 1. init degree (self-loop => start at 1.0)
__global__ void k_init() {
    int i = blockIdx.x * 256 + threadIdx.x;
    if (i < N_NODES) g_dinv[i] = 1.0f;
}

// 2. degree count at dst
__global__ void k_deg(const void* __restrict__ ei) {
    int t = blockIdx.x * 256 + threadIdx.x;
    if (t >= N_EDGES) return;
    int dst;
    if (g_is64) dst = (int)((const long long*)ei)[N_EDGES + t];
    else        dst = ((const int*)ei)[N_EDGES + t];
    atomicAdd(&g_dinv[dst], 1.0f);
}

// 3. deg -> rsqrt(deg) in place
__global__ void k_rsqrt() {
    int i = blockIdx.x * 256 + threadIdx.x;
    if (i < N_NODES) g_dinv[i] = rsqrtf(g_dinv[i]);
}

// 4. GEMM1: hs1[row][c] = (x[row] . W1[:,c]) * dinv[row] ; agg1 = hs1 (self loop)
//    block: 16 rows x 64 cols, blockDim(64,4), each thread 4 rows x 1 col
__global__ __launch_bounds__(256) void k_gemm1(const float* __restrict__ x,
                                               const float* __restrict__ W1) {
    __shared__ float Ws[IN_F * HID];      // 32 KB
    __shared__ float xs[16 * IN_F];       // 8 KB
    const int tx = threadIdx.x;           // col 0..63
    const int ty = threadIdx.y;           // row group 0..3
    const int tid = tx + 64 * ty;
    const int base = blockIdx.x * 16;

    #pragma unroll
    for (int i = tid; i < IN_F * HID; i += 256) Ws[i] = W1[i];
    #pragma unroll
    for (int i = tid; i < 16 * IN_F; i += 256) {
        int r = i >> 7, k = i & 127;
        xs[i] = x[(size_t)(base + r) * IN_F + k];
    }
    __syncthreads();

    float acc0 = 0.f, acc1 = 0.f, acc2 = 0.f, acc3 = 0.f;
    #pragma unroll
    for (int k4 = 0; k4 < IN_F; k4 += 4) {
        float4 x0 = *(const float4*)&xs[(ty * 4 + 0) * IN_F + k4];
        float4 x1 = *(const float4*)&xs[(ty * 4 + 1) * IN_F + k4];
        float4 x2 = *(const float4*)&xs[(ty * 4 + 2) * IN_F + k4];
        float4 x3 = *(const float4*)&xs[(ty * 4 + 3) * IN_F + k4];
        float w0 = Ws[(k4 + 0) * HID + tx];
        float w1 = Ws[(k4 + 1) * HID + tx];
        float w2 = Ws[(k4 + 2) * HID + tx];
        float w3 = Ws[(k4 + 3) * HID + tx];
        acc0 += x0.x * w0 + x0.y * w1 + x0.z * w2 + x0.w * w3;
        acc1 += x1.x * w0 + x1.y * w1 + x1.z * w2 + x1.w * w3;
        acc2 += x2.x * w0 + x2.y * w1 + x2.z * w2 + x2.w * w3;
        acc3 += x3.x * w0 + x3.y * w1 + x3.z * w2 + x3.w * w3;
    }
    float a[4] = {acc0, acc1, acc2, acc3};
    #pragma unroll
    for (int j = 0; j < 4; j++) {
        int row = base + ty * 4 + j;
        float hs = a[j] * g_dinv[row];
        g_hs1 [(size_t)row * HID + tx] = hs;
        g_agg1[(size_t)row * HID + tx] = hs;
    }
}

// 5. edge scatter layer1: agg1[dst] += hs1[src], one float4 chunk per thread
__global__ __launch_bounds__(256) void k_edge1(const void* __restrict__ ei) {
    int t = blockIdx.x * 256 + threadIdx.x;     // t < E*16
    int e = t >> 4, c = t & 15;
    int src, dst;
    if (g_is64) {
        const long long* p = (const long long*)ei;
        src = (int)p[e]; dst = (int)p[N_EDGES + e];
    } else {
        const int* p = (const int*)ei;
        src = p[e]; dst = p[N_EDGES + e];
    }
    float4 v = ((const float4*)g_hs1)[(size_t)src * 16 + c];
    float4* a = ((float4*)g_agg1) + ((size_t)dst * 16 + c);
    asm volatile("red.global.add.v4.f32 [%0], {%1,%2,%3,%4};"
                 :: "l"(a), "f"(v.x), "f"(v.y), "f"(v.z), "f"(v.w) : "memory");
}

// 6. finalize layer1 + GEMM2 fused:
//    r1 = relu(dinv*agg1 + b1); hs2 = (r1@W2)*dinv; agg2 = hs2 (self loop)
__global__ __launch_bounds__(256) void k_l2(const float* __restrict__ b1,
                                            const float* __restrict__ W2) {
    __shared__ float W2s[HID * NC];       // 4 KB
    __shared__ float r1s[16 * 65];        // padded
    const int tx = threadIdx.x;           // col 0..15
    const int ty = threadIdx.y;           // row 0..15
    const int tid = tx + 16 * ty;
    const int base = blockIdx.x * 16;

    #pragma unroll
    for (int i = tid; i < HID * NC; i += 256) W2s[i] = W2[i];
    #pragma unroll
    for (int i = tid; i < 16 * HID; i += 256) {
        int r = i >> 6, k = i & 63;
        int row = base + r;
        float v = g_dinv[row] * g_agg1[(size_t)row * HID + k] + b1[k];
        r1s[r * 65 + k] = fmaxf(v, 0.0f);
    }
    __syncthreads();

    float acc = 0.f;
    #pragma unroll
    for (int k = 0; k < HID; k++)
        acc += r1s[ty * 65 + k] * W2s[k * NC + tx];
    int row = base + ty;
    float hs = acc * g_dinv[row];
    g_hs2 [(size_t)row * NC + tx] = hs;
    g_agg2[(size_t)row * NC + tx] = hs;
}

// 7. edge scatter layer2
__global__ __launch_bounds__(256) void k_edge2(const void* __restrict__ ei) {
    int t = blockIdx.x * 256 + threadIdx.x;     // t < E*4
    int e = t >> 2, c = t & 3;
    int src, dst;
    if (g_is64) {
        const long long* p = (const long long*)ei;
        src = (int)p[e]; dst = (int)p[N_EDGES + e];
    } else {
        const int* p = (const int*)ei;
        src = p[e]; dst = p[N_EDGES + e];
    }
    float4 v = ((const float4*)g_hs2)[(size_t)src * 4 + c];
    float4* a = ((float4*)g_agg2) + ((size_t)dst * 4 + c);
    asm volatile("red.global.add.v4.f32 [%0], {%1,%2,%3,%4};"
                 :: "l"(a), "f"(v.x), "f"(v.y), "f"(v.z), "f"(v.w) : "memory");
}

// 8. finalize layer2: out = dinv*agg2 + b2
__global__ __launch_bounds__(256) void k_fin2(const float* __restrict__ b2,
                                              float* __restrict__ out) {
    int t = blockIdx.x * 256 + threadIdx.x;
    if (t >= N_NODES * NC) return;
    out[t] = g_dinv[t >> 4] * g_agg2[t] + b2[t & 15];
}

extern "C" void kernel_launch(void* const* d_in, const int* in_sizes, int n_in,
                              void* d_out, int out_size) {
    const float* x  = (const float*)d_in[0];
    const void*  ei = d_in[1];
    const float* W1 = (const float*)d_in[2];
    const float* b1 = (const float*)d_in[3];
    const float* W2 = (const float*)d_in[4];
    const float* b2 = (const float*)d_in[5];
    float* out = (float*)d_out;

    k_detect<<<1, 256>>>((const long long*)ei);
    k_init  <<<(N_NODES + 255) / 256, 256>>>();
    k_deg   <<<(N_EDGES + 255) / 256, 256>>>(ei);
    k_rsqrt <<<(N_NODES + 255) / 256, 256>>>();
    k_gemm1 <<<N_NODES / 16, dim3(64, 4)>>>(x, W1);
    k_edge1 <<<(N_EDGES * 16) / 256, 256>>>(ei);
    k_l2    <<<N_NODES / 16, dim3(16, 16)>>>(b1, W2);
    k_edge2 <<<(N_EDGES * 4) / 256, 256>>>(ei);
    k_fin2  <<<(N_NODES * NC + 255) / 256, 256>>>(b2, out);
}

// round 6
// speedup vs baseline: 1.4137x; 1.4137x over previous
#include <cuda_runtime.h>

#define N_NODES 100000
#define N_EDGES 3200000
#define IN_F 128
#define HID 64
#define NC 16
#define NB ((N_NODES + 255) / 256)   // 391

// Scratch (static device globals — no allocation allowed)
__device__ __align__(16) float g_dinv[N_NODES];
__device__ __align__(16) float g_hs1 [N_NODES * HID];   // (x@W1)*dinv[row]
__device__ __align__(16) float g_hs2 [N_NODES * NC];    // (r1@W2)*dinv[row]
__device__ int g_cnt[N_NODES];        // in-degree (edges only)
__device__ int g_cur[N_NODES];        // fill cursor
__device__ int g_off[N_NODES + 1];    // CSR offsets (by dst)
__device__ int g_bsum[NB];
__device__ int g_boff[NB];
__device__ int g_ecsr[N_EDGES];       // src ids grouped by dst
__device__ int g_is64;

// ---------------------------------------------------------------------------
// 0. detect int64 vs int32 edge_index (reads only first 4096 src entries)
__global__ void k_detect(const long long* __restrict__ ei) {
    __shared__ int bad;
    if (threadIdx.x == 0) bad = 0;
    __syncthreads();
    for (int i = threadIdx.x; i < 4096; i += 256) {
        long long s = ei[i];
        if (s < 0 || s >= (long long)N_NODES) atomicOr(&bad, 1);
    }
    __syncthreads();
    if (threadIdx.x == 0) g_is64 = bad ? 0 : 1;
}

// 1. zero counters
__global__ void k_zero() {
    int i = blockIdx.x * 256 + threadIdx.x;
    if (i < N_NODES) { g_cnt[i] = 0; g_cur[i] = 0; }
}

// 2. degree count at dst (int atomics)
__global__ void k_deg(const void* __restrict__ ei) {
    int t = blockIdx.x * 256 + threadIdx.x;
    if (t >= N_EDGES) return;
    int dst;
    if (g_is64) dst = (int)((const long long*)ei)[N_EDGES + t];
    else        dst = ((const int*)ei)[N_EDGES + t];
    atomicAdd(&g_cnt[dst], 1);
}

// 3a. per-block sums
__global__ void k_scan1() {
    __shared__ int s[256];
    int t = threadIdx.x;
    int i = blockIdx.x * 256 + t;
    s[t] = (i < N_NODES) ? g_cnt[i] : 0;
    __syncthreads();
    #pragma unroll
    for (int o = 128; o > 0; o >>= 1) {
        if (t < o) s[t] += s[t + o];
        __syncthreads();
    }
    if (t == 0) g_bsum[blockIdx.x] = s[0];
}

// 3b. scan of block sums (single block, 512 threads, NB=391 <= 512)
__global__ void k_scan2() {
    __shared__ int s[512];
    int t = threadIdx.x;
    int mine = (t < NB) ? g_bsum[t] : 0;
    s[t] = mine;
    __syncthreads();
    #pragma unroll
    for (int o = 1; o < 512; o <<= 1) {
        int v = (t >= o) ? s[t - o] : 0;
        __syncthreads();
        s[t] += v;
        __syncthreads();
    }
    if (t < NB) g_boff[t] = s[t] - mine;   // exclusive
}

// 3c. within-block exclusive scan -> offsets; also dinv = rsqrt(cnt+1)
__global__ void k_scan3() {
    __shared__ int s[256];
    int t = threadIdx.x;
    int i = blockIdx.x * 256 + t;
    int c = (i < N_NODES) ? g_cnt[i] : 0;
    s[t] = c;
    __syncthreads();
    #pragma unroll
    for (int o = 1; o < 256; o <<= 1) {
        int v = (t >= o) ? s[t - o] : 0;
        __syncthreads();
        s[t] += v;
        __syncthreads();
    }
    if (i < N_NODES) {
        g_off[i] = g_boff[blockIdx.x] + s[t] - c;
        g_dinv[i] = rsqrtf((float)(c + 1));
    }
    if (i == 0) g_off[N_NODES] = N_EDGES;
}

// 4. CSR fill: bucket src by dst
__global__ void k_fill(const void* __restrict__ ei) {
    int t = blockIdx.x * 256 + threadIdx.x;
    if (t >= N_EDGES) return;
    int src, dst;
    if (g_is64) {
        const long long* p = (const long long*)ei;
        src = (int)p[t]; dst = (int)p[N_EDGES + t];
    } else {
        const int* p = (const int*)ei;
        src = p[t]; dst = p[N_EDGES + t];
    }
    int pos = atomicAdd(&g_cur[dst], 1);
    g_ecsr[g_off[dst] + pos] = src;
}

// 5. GEMM1: hs1[row][c] = (x[row] . W1[:,c]) * dinv[row]
__global__ __launch_bounds__(256) void k_gemm1(const float* __restrict__ x,
                                               const float* __restrict__ W1) {
    __shared__ float Ws[IN_F * HID];      // 32 KB
    __shared__ float xs[16 * IN_F];       // 8 KB
    const int tx = threadIdx.x;           // col 0..63
    const int ty = threadIdx.y;           // row group 0..3
    const int tid = tx + 64 * ty;
    const int base = blockIdx.x * 16;

    #pragma unroll
    for (int i = tid; i < IN_F * HID; i += 256) Ws[i] = W1[i];
    #pragma unroll
    for (int i = tid; i < 16 * IN_F; i += 256) {
        int r = i >> 7, k = i & 127;
        xs[i] = x[(size_t)(base + r) * IN_F + k];
    }
    __syncthreads();

    float acc0 = 0.f, acc1 = 0.f, acc2 = 0.f, acc3 = 0.f;
    #pragma unroll
    for (int k4 = 0; k4 < IN_F; k4 += 4) {
        float4 x0 = *(const float4*)&xs[(ty * 4 + 0) * IN_F + k4];
        float4 x1 = *(const float4*)&xs[(ty * 4 + 1) * IN_F + k4];
        float4 x2 = *(const float4*)&xs[(ty * 4 + 2) * IN_F + k4];
        float4 x3 = *(const float4*)&xs[(ty * 4 + 3) * IN_F + k4];
        float w0 = Ws[(k4 + 0) * HID + tx];
        float w1 = Ws[(k4 + 1) * HID + tx];
        float w2 = Ws[(k4 + 2) * HID + tx];
        float w3 = Ws[(k4 + 3) * HID + tx];
        acc0 += x0.x * w0 + x0.y * w1 + x0.z * w2 + x0.w * w3;
        acc1 += x1.x * w0 + x1.y * w1 + x1.z * w2 + x1.w * w3;
        acc2 += x2.x * w0 + x2.y * w1 + x2.z * w2 + x2.w * w3;
        acc3 += x3.x * w0 + x3.y * w1 + x3.z * w2 + x3.w * w3;
    }
    float a[4] = {acc0, acc1, acc2, acc3};
    #pragma unroll
    for (int j = 0; j < 4; j++) {
        int row = base + ty * 4 + j;
        g_hs1[(size_t)row * HID + tx] = a[j] * g_dinv[row];
    }
}

// 6. Layer-1 aggregation (CSR gather) fused with relu+bias+GEMM2:
//    acc = hs1[n] + sum_{src in csr[n]} hs1[src]
//    r1  = relu(acc*dinv[n] + b1);  hs2[n] = (r1 @ W2) * dinv[n]
//    16-thread groups, 16 nodes/block
__global__ __launch_bounds__(256) void k_agg1(const float* __restrict__ b1,
                                              const float* __restrict__ W2) {
    __shared__ float W2s[HID * NC];       // 4 KB
    __shared__ float r1s[16][HID];        // 4 KB
    const int t = threadIdx.x;
    const int g = t >> 4;
    const int lane = t & 15;
    #pragma unroll
    for (int i = t; i < HID * NC; i += 256) W2s[i] = W2[i];

    const int n = blockIdx.x * 16 + g;    // grid = 6250, exact
    const int start = g_off[n], end = g_off[n + 1];
    float4 acc = ((const float4*)g_hs1)[(size_t)n * 16 + lane];  // self loop
    const unsigned hm = 0xFFFFu << (t & 16);

    int j = start;
    for (; j + 16 <= end; j += 16) {
        int sv = g_ecsr[j + lane];
        #pragma unroll
        for (int q = 0; q < 16; q++) {
            int s = __shfl_sync(hm, sv, q, 16);
            float4 v = ((const float4*)g_hs1)[(size_t)s * 16 + lane];
            acc.x += v.x; acc.y += v.y; acc.z += v.z; acc.w += v.w;
        }
    }
    int rem = end - j;
    if (rem > 0) {
        int sv = (lane < rem) ? g_ecsr[j + lane] : 0;
        for (int q = 0; q < rem; q++) {
            int s = __shfl_sync(hm, sv, q, 16);
            float4 v = ((const float4*)g_hs1)[(size_t)s * 16 + lane];
            acc.x += v.x; acc.y += v.y; acc.z += v.z; acc.w += v.w;
        }
    }

    const float d = g_dinv[n];
    float4 bb = ((const float4*)b1)[lane];
    r1s[g][lane * 4 + 0] = fmaxf(acc.x * d + bb.x, 0.f);
    r1s[g][lane * 4 + 1] = fmaxf(acc.y * d + bb.y, 0.f);
    r1s[g][lane * 4 + 2] = fmaxf(acc.z * d + bb.z, 0.f);
    r1s[g][lane * 4 + 3] = fmaxf(acc.w * d + bb.w, 0.f);
    __syncthreads();

    float o = 0.f;
    #pragma unroll
    for (int k = 0; k < HID; k++)
        o += r1s[g][k] * W2s[k * NC + lane];
    g_hs2[(size_t)n * NC + lane] = o * d;
}

// 7. Layer-2 aggregation fused with final bias; writes d_out.
//    4-thread groups, 64 nodes/block
__global__ __launch_bounds__(256) void k_agg2(const float* __restrict__ b2,
                                              float* __restrict__ out) {
    const int t = threadIdx.x;
    const int g = t >> 2;
    const int lane = t & 3;
    const int n = blockIdx.x * 64 + g;
    if (n >= N_NODES) return;

    const int start = g_off[n], end = g_off[n + 1];
    float4 acc = ((const float4*)g_hs2)[(size_t)n * 4 + lane];   // self loop
    const int li = t & 31;
    const unsigned qm = 0xFu << (li & 28);

    int j = start;
    for (; j + 4 <= end; j += 4) {
        int sv = g_ecsr[j + lane];
        #pragma unroll
        for (int q = 0; q < 4; q++) {
            int s = __shfl_sync(qm, sv, q, 4);
            float4 v = ((const float4*)g_hs2)[(size_t)s * 4 + lane];
            acc.x += v.x; acc.y += v.y; acc.z += v.z; acc.w += v.w;
        }
    }
    int rem = end - j;
    if (rem > 0) {
        int sv = (lane < rem) ? g_ecsr[j + lane] : 0;
        for (int q = 0; q < rem; q++) {
            int s = __shfl_sync(qm, sv, q, 4);
            float4 v = ((const float4*)g_hs2)[(size_t)s * 4 + lane];
            acc.x += v.x; acc.y += v.y; acc.z += v.z; acc.w += v.w;
        }
    }

    const float d = g_dinv[n];
    float4 bb = ((const float4*)b2)[lane];
    float4 r;
    r.x = acc.x * d + bb.x;
    r.y = acc.y * d + bb.y;
    r.z = acc.z * d + bb.z;
    r.w = acc.w * d + bb.w;
    ((float4*)out)[(size_t)n * 4 + lane] = r;
}

extern "C" void kernel_launch(void* const* d_in, const int* in_sizes, int n_in,
                              void* d_out, int out_size) {
    const float* x  = (const float*)d_in[0];
    const void*  ei = d_in[1];
    const float* W1 = (const float*)d_in[2];
    const float* b1 = (const float*)d_in[3];
    const float* W2 = (const float*)d_in[4];
    const float* b2 = (const float*)d_in[5];
    float* out = (float*)d_out;

    k_detect<<<1, 256>>>((const long long*)ei);
    k_zero  <<<NB, 256>>>();
    k_deg   <<<(N_EDGES + 255) / 256, 256>>>(ei);
    k_scan1 <<<NB, 256>>>();
    k_scan2 <<<1, 512>>>();
    k_scan3 <<<NB, 256>>>();
    k_fill  <<<(N_EDGES + 255) / 256, 256>>>(ei);
    k_gemm1 <<<N_NODES / 16, dim3(64, 4)>>>(x, W1);
    k_agg1  <<<N_NODES / 16, 256>>>(b1, W2);
    k_agg2  <<<(N_NODES + 63) / 64, 256>>>(b2, out);
}